// round 11
// baseline (speedup 1.0000x reference)
#include <cuda_runtime.h>
#include <cuda_fp16.h>
#include <stdint.h>

#define M_DIM 2048
#define N_DIM 8192
#define K_DIM 8192

__device__ __align__(128) __half g_A[(size_t)M_DIM * K_DIM];   // 33.5 MB
__device__ __align__(128) __half g_B[(size_t)N_DIM * K_DIM];   // 134 MB

// sync block: [0]=tile ticket, [1]=adone, [2..65]=sdone[64]
__device__ unsigned g_sync[66];

#define GRID   296
#define NPROD  128
#define NTILES 1024

// ---------------------------------------------------------------------------
// GEMM tile config (identical to R10)
// ---------------------------------------------------------------------------
#define BM 128
#define BN 128
#define BK 64
#define NSTAGE 3
#define NITER (K_DIM / BK)               // 128
#define A_BYTES (BM * BK * 2)
#define B_BYTES (BN * BK * 2)
#define STAGE_BYTES (A_BYTES + B_BYTES)
#define GEMM_SMEM (NSTAGE * STAGE_BYTES) // 98304

__device__ __forceinline__ uint32_t smem_u32(const void* p) {
    uint32_t a;
    asm("{ .reg .u64 t; cvta.to.shared.u64 t, %1; cvt.u32.u64 %0, t; }"
        : "=r"(a) : "l"(p));
    return a;
}

__device__ __forceinline__ uint32_t swz(uint32_t base, int row, int chunk) {
    return base + row * 128 + (((chunk ^ row) & 7) << 4);
}

__device__ __forceinline__ void cp16(uint32_t dst, const void* src) {
    asm volatile("cp.async.cg.shared.global [%0], [%1], 16;\n"
                 :: "r"(dst), "l"(src));
}

__device__ __forceinline__ void ldsm4(uint32_t* r, uint32_t addr) {
    asm volatile("ldmatrix.sync.aligned.m8n8.x4.shared.b16 {%0,%1,%2,%3}, [%4];"
                 : "=r"(r[0]), "=r"(r[1]), "=r"(r[2]), "=r"(r[3]) : "r"(addr));
}

__device__ __forceinline__ void mma16816(float* c, const uint32_t* a,
                                         const uint32_t* b) {
    asm volatile(
        "mma.sync.aligned.m16n8k16.row.col.f32.f16.f16.f32 "
        "{%0,%1,%2,%3}, {%4,%5,%6,%7}, {%8,%9}, {%0,%1,%2,%3};\n"
        : "+f"(c[0]), "+f"(c[1]), "+f"(c[2]), "+f"(c[3])
        : "r"(a[0]), "r"(a[1]), "r"(a[2]), "r"(a[3]), "r"(b[0]), "r"(b[1]));
}

__device__ __forceinline__ unsigned ld_acq(const unsigned* p) {
    unsigned v;
    asm volatile("ld.global.acquire.gpu.u32 %0, [%1];" : "=r"(v) : "l"(p) : "memory");
    return v;
}

__device__ __forceinline__ void red_release(unsigned* p) {
    asm volatile("red.release.gpu.global.add.u32 [%0], %1;" :: "l"(p), "r"(1u) : "memory");
}

// ---------------------------------------------------------------------------
// Producer bodies
// ---------------------------------------------------------------------------
__device__ __forceinline__ void convert_a_item(const float* __restrict__ x,
                                               int a, int tid) {
    size_t i = (size_t)a * 2048 + (size_t)tid * 16;
    float4 v0 = *reinterpret_cast<const float4*>(x + i);
    float4 v1 = *reinterpret_cast<const float4*>(x + i + 4);
    float4 v2 = *reinterpret_cast<const float4*>(x + i + 8);
    float4 v3 = *reinterpret_cast<const float4*>(x + i + 12);
    __half2 h0 = __floats2half2_rn(v0.x, v0.y);
    __half2 h1 = __floats2half2_rn(v0.z, v0.w);
    __half2 h2 = __floats2half2_rn(v1.x, v1.y);
    __half2 h3 = __floats2half2_rn(v1.z, v1.w);
    __half2 h4 = __floats2half2_rn(v2.x, v2.y);
    __half2 h5 = __floats2half2_rn(v2.z, v2.w);
    __half2 h6 = __floats2half2_rn(v3.x, v3.y);
    __half2 h7 = __floats2half2_rn(v3.z, v3.w);
    uint4 o0, o1;
    o0.x = *reinterpret_cast<uint32_t*>(&h0);
    o0.y = *reinterpret_cast<uint32_t*>(&h1);
    o0.z = *reinterpret_cast<uint32_t*>(&h2);
    o0.w = *reinterpret_cast<uint32_t*>(&h3);
    o1.x = *reinterpret_cast<uint32_t*>(&h4);
    o1.y = *reinterpret_cast<uint32_t*>(&h5);
    o1.z = *reinterpret_cast<uint32_t*>(&h6);
    o1.w = *reinterpret_cast<uint32_t*>(&h7);
    *reinterpret_cast<uint4*>(&g_A[i]) = o0;
    *reinterpret_cast<uint4*>(&g_A[i + 8]) = o1;
}

__device__ __forceinline__ void dequant_chunk(const int* __restrict__ p,
                                              const float* __restrict__ cb,
                                              int n, int c, int tid) {
    int t = n * 32768 + c * 128 + tid;                  // 32 weights per thread
    const int4* p4 = reinterpret_cast<const int4*>(p) + (size_t)t * 3;
    int4 pa = p4[0], pb = p4[1], pc = p4[2];
    int by[12] = {pa.x, pa.y, pa.z, pa.w, pb.x, pb.y, pb.z, pb.w,
                  pc.x, pc.y, pc.z, pc.w};

    const float4* c4 = reinterpret_cast<const float4*>(cb) + (size_t)(t >> 2) * 2;
    float4 f0 = __ldg(c4), f1 = __ldg(c4 + 1);
    uint64_t t0 = (uint64_t)__half_as_ushort(__float2half_rn(f0.x))
                | ((uint64_t)__half_as_ushort(__float2half_rn(f0.y)) << 16)
                | ((uint64_t)__half_as_ushort(__float2half_rn(f0.z)) << 32)
                | ((uint64_t)__half_as_ushort(__float2half_rn(f0.w)) << 48);
    uint64_t t1 = (uint64_t)__half_as_ushort(__float2half_rn(f1.x))
                | ((uint64_t)__half_as_ushort(__float2half_rn(f1.y)) << 16)
                | ((uint64_t)__half_as_ushort(__float2half_rn(f1.z)) << 32)
                | ((uint64_t)__half_as_ushort(__float2half_rn(f1.w)) << 48);

    uint4* dst = reinterpret_cast<uint4*>(g_B + (size_t)t * 32);
#pragma unroll
    for (int g = 0; g < 4; g++) {
        unsigned bits = (unsigned)by[3 * g] | ((unsigned)by[3 * g + 1] << 8)
                      | ((unsigned)by[3 * g + 2] << 16);
        uint32_t hv[8];
#pragma unroll
        for (int j = 0; j < 8; j++) {
            int idx = (bits >> (3 * j)) & 7;
            uint64_t tab = (idx & 4) ? t1 : t0;
            hv[j] = (uint32_t)(tab >> ((idx & 3) << 4)) & 0xFFFFu;
        }
        uint4 o;
        o.x = hv[0] | (hv[1] << 16);
        o.y = hv[2] | (hv[3] << 16);
        o.z = hv[4] | (hv[5] << 16);
        o.w = hv[6] | (hv[7] << 16);
        dst[g] = o;
    }
}

// ---------------------------------------------------------------------------
// Fused kernel
// ---------------------------------------------------------------------------
__global__ void __launch_bounds__(128, 2) fused_kernel(
    const float* __restrict__ x, const int* __restrict__ p,
    const float* __restrict__ cb, float* __restrict__ y) {
    extern __shared__ char smem[];
    const uint32_t sb = smem_u32(smem);
    const int tid = threadIdx.x;
    const int bid = blockIdx.x;
    const int w = tid >> 5, lane = tid & 31;
    const int wm = (w & 1) * 64;
    const int wn = (w >> 1) * 64;

    unsigned* ticket = &g_sync[0];
    unsigned* adone  = &g_sync[1];
    unsigned* sdone  = &g_sync[2];

    // ---- Phase A: all CTAs convert x -> fp16 (grid-stride) ----
    for (int a = bid; a < 8192; a += GRID)
        convert_a_item(x, a, tid);
    __threadfence();
    __syncthreads();
    if (tid == 0) red_release(adone);

    // ---- Phase B: producers dequant W stripe-by-stripe ----
    if (bid < NPROD) {
#pragma unroll 1
        for (int n = 0; n < 64; n++) {
#pragma unroll
            for (int ci = 0; ci < 2; ci++)               // 256 chunks / 128 prods
                dequant_chunk(p, cb, n, bid + ci * NPROD, tid);
            __threadfence();
            __syncthreads();
            if (tid == 0) red_release(&sdone[n]);
        }
    }

    // ---- Consumer: ticketed GEMM tiles ----
    __shared__ unsigned s_tile;
    while (true) {
        __syncthreads();                    // also fences previous tile's smem use
        if (tid == 0) s_tile = atomicAdd(ticket, 1);
        __syncthreads();
        const unsigned t = s_tile;
        if (t >= NTILES) break;
        const int bm = (int)(t & 15) * BM;
        const int bn = (int)(t >> 4) * BN;
        const int n = (int)(t >> 4);

        if (tid == 0) {
            while (ld_acq(adone) < GRID) __nanosleep(128);
            while (ld_acq(&sdone[n]) < NPROD) __nanosleep(128);
        }
        __syncthreads();

        // ------- GEMM tile (R10 body) -------
        float acc[4][8][4];
#pragma unroll
        for (int i = 0; i < 4; i++)
#pragma unroll
            for (int j = 0; j < 8; j++)
#pragma unroll
                for (int r = 0; r < 4; r++) acc[i][j][r] = 0.0f;

        auto load_A = [&](int buf, int chunk) {
            const int k0 = chunk * BK;
            const uint32_t abase = sb + buf * STAGE_BYTES;
#pragma unroll
            for (int i = 0; i < 8; i++) {
                int c = tid + i * 128;
                int row = c >> 3, ch = c & 7;
                cp16(swz(abase, row, ch),
                     g_A + (size_t)(bm + row) * K_DIM + k0 + ch * 8);
            }
        };
        auto load_B = [&](int buf, int chunk) {
            const int k0 = chunk * BK;
            const uint32_t bbase = sb + buf * STAGE_BYTES + A_BYTES;
#pragma unroll
            for (int i = 0; i < 8; i++) {
                int c = tid + i * 128;
                int row = c >> 3, ch = c & 7;
                cp16(swz(bbase, row, ch),
                     g_B + (size_t)(bn + row) * K_DIM + k0 + ch * 8);
            }
            asm volatile("cp.async.commit_group;" ::: "memory");
        };

        load_A(0, 0); load_B(0, 0);
        load_A(1, 1); load_B(1, 1);

        uint32_t ra[2][4][4], rb[2][4][4];

        auto ldfrag = [&](uint32_t abase, uint32_t bbase, int kk, int pb) {
#pragma unroll
            for (int mi = 0; mi < 4; mi++) {
                int row = wm + mi * 16 + (lane & 15);
                int ch = kk * 2 + (lane >> 4);
                ldsm4(ra[pb][mi], swz(abase, row, ch));
            }
#pragma unroll
            for (int np = 0; np < 4; np++) {
                int row = wn + np * 16 + (lane & 7) + ((lane >> 4) << 3);
                int ch = kk * 2 + ((lane >> 3) & 1);
                ldsm4(rb[pb][np], swz(bbase, row, ch));
            }
        };

        auto mma_block = [&](int pb) {
#pragma unroll
            for (int mi = 0; mi < 4; mi++)
#pragma unroll
                for (int ni = 0; ni < 8; ni++)
                    mma16816(acc[mi][ni], ra[pb][mi],
                             &rb[pb][ni >> 1][(ni & 1) * 2]);
        };

        auto body = [&](int it, int buf) {
            if (it < NITER - 2)
                asm volatile("cp.async.wait_group 1;" ::: "memory");
            else
                asm volatile("cp.async.wait_group 0;" ::: "memory");
            __syncthreads();

            const uint32_t abase = sb + buf * STAGE_BYTES;
            const uint32_t bbase = abase + A_BYTES;
            const int j = it + 2;
            const int jb = (buf + 2) % NSTAGE;

            ldfrag(abase, bbase, 0, 0);
            if (j < NITER) load_A(jb, j);
            ldfrag(abase, bbase, 1, 1);
            if (j < NITER) load_B(jb, j);

            mma_block(0);
            ldfrag(abase, bbase, 2, 0);
            mma_block(1);
            ldfrag(abase, bbase, 3, 1);
            mma_block(0);
            mma_block(1);
        };

        int it = 0;
#pragma unroll 1
        for (int tt = 0; tt < (NITER - 2) / NSTAGE; tt++) {
            body(it, 0);
            body(it + 1, 1);
            body(it + 2, 2);
            it += 3;
        }
        body(126, 0);
        body(127, 1);

#pragma unroll
        for (int mi = 0; mi < 4; mi++) {
#pragma unroll
            for (int ni = 0; ni < 8; ni++) {
                int row = bm + wm + mi * 16 + (lane >> 2);
                int col = bn + wn + ni * 8 + (lane & 3) * 2;
                *reinterpret_cast<float2*>(&y[(size_t)row * N_DIM + col]) =
                    make_float2(acc[mi][ni][0], acc[mi][ni][1]);
                *reinterpret_cast<float2*>(&y[(size_t)(row + 8) * N_DIM + col]) =
                    make_float2(acc[mi][ni][2], acc[mi][ni][3]);
            }
        }
    }
}

// ---------------------------------------------------------------------------
extern "C" void kernel_launch(void* const* d_in, const int* in_sizes, int n_in,
                              void* d_out, int out_size) {
    const float* x  = (const float*)d_in[0];
    const int*   p  = (const int*)d_in[1];
    const float* cb = (const float*)d_in[2];
    float* y = (float*)d_out;

    // Zero sync counters (captured into the graph; runs every replay)
    void* sync_ptr = nullptr;
    cudaGetSymbolAddress(&sync_ptr, g_sync);
    cudaMemsetAsync(sync_ptr, 0, sizeof(unsigned) * 66, 0);

    cudaFuncSetAttribute(fused_kernel,
                         cudaFuncAttributeMaxDynamicSharedMemorySize, GEMM_SMEM);
    fused_kernel<<<GRID, 128, GEMM_SMEM>>>(x, p, cb, y);
}